// round 15
// baseline (speedup 1.0000x reference)
#include <cuda_runtime.h>
#include <cuda_fp16.h>
#include <math.h>

#define MAXN 65536
#define MAXB 1024
#define LN_EPS 1e-5f
#define CLAMP_MIN 1e-5f

// Scratch (device globals — no allocation allowed)
__device__ unsigned char g_pred[MAXN];
__device__ __half g_h16[(size_t)MAXN * 128];           // fp16 copy of h
__device__ float g_plog[40];                           // k*log(clip(k)) table
__device__ float g_f1[MAXN];
__device__ float g_f2[MAXN];
__device__ double g_part[4 * MAXB];
__device__ float g_stats[4];
__device__ unsigned int g_ctr;                         // feat-done counter (zero-init, self-resetting)
__device__ unsigned int g_predctr;                     // pred-done counter (zero-init, self-resetting)

__device__ __forceinline__ void addf32x2(unsigned long long& a, unsigned long long b) {
    asm("add.rn.f32x2 %0, %1, %2;" : "=l"(a) : "l"(a), "l"(b));
}

// ---------------------------------------------------------------------------
// Kernel B (fast path, R12 structure): ONE kernel, TWO disjoint roles:
//  feat blocks (blockIdx < nbfeat=196): pred(their 256 nodes) -> signal ->
//    spin till all pred slices done (all wave-1, ~1.5us) -> histogram ->
//    fused partials + last-block stats. NO conversion.
//  conv blocks (the rest): grid-stride h->fp16 conversion only (DRAM-bound).
// Deadlock-free: conv blocks never wait; feat blocks wait only on feat blocks.
// ---------------------------------------------------------------------------
__global__ void __launch_bounds__(256)
k_featconv(const int* __restrict__ nbr, const float* __restrict__ logits,
           const float* __restrict__ h, int n, int nbfeat, int nF4) {
    int t = threadIdx.x;
    bool isfeat = (blockIdx.x < (unsigned)nbfeat);

    if (!isfeat) {
        // ---- conversion-only path: 8 independent loads in flight ----
        int cb = blockIdx.x - nbfeat;
        int nconv = gridDim.x - nbfeat;
        int gi = cb * 256 + t;
        int gsz = nconv * 256;
        const float4* hp = (const float4*)h;
        uint2* dst = (uint2*)g_h16;
        int idx = gi;
        for (; idx + 7 * gsz < nF4; idx += 8 * gsz) {
            float4 v[8];
            #pragma unroll
            for (int k = 0; k < 8; k++) v[k] = __ldg(&hp[idx + k * gsz]);
            #pragma unroll
            for (int k = 0; k < 8; k++) {
                uint2 pk;
                __half2 c;
                c = __floats2half2_rn(v[k].x, v[k].y); pk.x = *(unsigned int*)&c;
                c = __floats2half2_rn(v[k].z, v[k].w); pk.y = *(unsigned int*)&c;
                dst[idx + k * gsz] = pk;
            }
        }
        for (; idx < nF4; idx += gsz) {
            float4 v = __ldg(&hp[idx]);
            __half2 lo = __floats2half2_rn(v.x, v.y);
            __half2 hi = __floats2half2_rn(v.z, v.w);
            uint2 pk;
            pk.x = *(unsigned int*)&lo;
            pk.y = *(unsigned int*)&hi;
            dst[idx] = pk;
        }
        return;
    }

    // ---- feat path ----
    {
        int i = blockIdx.x * 256 + t;
        if (i < n) {
            const float4* lrow = (const float4*)(logits + (size_t)i * 16);
            float best = -INFINITY;
            int bi = 0;
            #pragma unroll
            for (int q = 0; q < 4; q++) {
                float4 v = __ldg(&lrow[q]);
                float vv[4] = {v.x, v.y, v.z, v.w};
                #pragma unroll
                for (int r = 0; r < 4; r++)
                    if (vv[r] > best) { best = vv[r]; bi = q * 4 + r; }
            }
            g_pred[i] = (unsigned char)bi;
        }
        if (blockIdx.x == 0 && t < 33) {
            float p = fmaxf((float)t, CLAMP_MIN);
            g_plog[t] = p * logf(p);
        }
        __threadfence();
        __syncthreads();
        if (t == 0) atomicAdd(&g_predctr, 1u);
    }

    if (t == 0) {
        while (atomicAdd(&g_predctr, 0u) < (unsigned)nbfeat) __nanosleep(64);
    }
    __syncthreads();
    __threadfence();   // acquire: preds visible

    float f1 = 0.f, f2 = 0.f;
    int i = blockIdx.x * 256 + t;
    if (i < n) {
        unsigned int cnt[4] = {0u, 0u, 0u, 0u};
        const int4* row4 = (const int4*)(nbr + (size_t)i * 32);
        #pragma unroll
        for (int q = 0; q < 8; q++) {
            int4 v = __ldg(&row4[q]);
            int jj[4] = {v.x, v.y, v.z, v.w};
            #pragma unroll
            for (int r = 0; r < 4; r++) {
                int p = (int)g_pred[jj[r]];
                cnt[p >> 2] += 1u << ((p & 3) * 8);
            }
        }
        int cp = (int)g_pred[i];
        f1 = (float)((cnt[cp >> 2] >> ((cp & 3) * 8)) & 0xffu);
        float s = 0.f;
        #pragma unroll
        for (int w = 0; w < 4; w++) {
            unsigned int v = cnt[w];
            s += __ldg(&g_plog[v & 0xffu]);
            s += __ldg(&g_plog[(v >> 8) & 0xffu]);
            s += __ldg(&g_plog[(v >> 16) & 0xffu]);
            s += __ldg(&g_plog[(v >> 24) & 0xffu]);
        }
        f2 = -s;
        g_f1[i] = f1;
        g_f2[i] = f2;
    }

    // fused block reduction (deterministic)
    double s1 = (double)f1, q1 = (double)f1 * f1;
    double s2 = (double)f2, q2 = (double)f2 * f2;
    __shared__ double sh[4][8];
    __shared__ int s_last;
    int lane = t & 31, wid = t >> 5;
    for (int o = 16; o; o >>= 1) {
        s1 += __shfl_down_sync(0xffffffffu, s1, o);
        q1 += __shfl_down_sync(0xffffffffu, q1, o);
        s2 += __shfl_down_sync(0xffffffffu, s2, o);
        q2 += __shfl_down_sync(0xffffffffu, q2, o);
    }
    if (lane == 0) { sh[0][wid] = s1; sh[1][wid] = q1; sh[2][wid] = s2; sh[3][wid] = q2; }
    __syncthreads();
    if (t == 0) {
        s1 = 0; q1 = 0; s2 = 0; q2 = 0;
        #pragma unroll
        for (int k = 0; k < 8; k++) { s1 += sh[0][k]; q1 += sh[1][k]; s2 += sh[2][k]; q2 += sh[3][k]; }
        g_part[0 * MAXB + blockIdx.x] = s1;
        g_part[1 * MAXB + blockIdx.x] = q1;
        g_part[2 * MAXB + blockIdx.x] = s2;
        g_part[3 * MAXB + blockIdx.x] = q2;
        __threadfence();
        unsigned int done = atomicAdd(&g_ctr, 1u);
        s_last = (done == (unsigned int)(nbfeat - 1)) ? 1 : 0;
    }
    __syncthreads();

    if (s_last) {
        __threadfence();
        double r1 = 0, p1 = 0, r2 = 0, p2 = 0;
        for (int b = t; b < nbfeat; b += 256) {
            r1 += g_part[0 * MAXB + b];
            p1 += g_part[1 * MAXB + b];
            r2 += g_part[2 * MAXB + b];
            p2 += g_part[3 * MAXB + b];
        }
        for (int o = 16; o; o >>= 1) {
            r1 += __shfl_down_sync(0xffffffffu, r1, o);
            p1 += __shfl_down_sync(0xffffffffu, p1, o);
            r2 += __shfl_down_sync(0xffffffffu, r2, o);
            p2 += __shfl_down_sync(0xffffffffu, p2, o);
        }
        if (lane == 0) { sh[0][wid] = r1; sh[1][wid] = p1; sh[2][wid] = r2; sh[3][wid] = p2; }
        __syncthreads();
        if (t == 0) {
            r1 = 0; p1 = 0; r2 = 0; p2 = 0;
            #pragma unroll
            for (int k = 0; k < 8; k++) { r1 += sh[0][k]; p1 += sh[1][k]; r2 += sh[2][k]; p2 += sh[3][k]; }
            double inv_n = 1.0 / (double)n;
            double m1 = r1 * inv_n, m2 = r2 * inv_n;
            double v1 = p1 * inv_n - m1 * m1;
            double v2 = p2 * inv_n - m2 * m2;
            g_stats[0] = (float)m1;
            g_stats[1] = (float)(1.0 / sqrt(v1 + (double)LN_EPS));
            g_stats[2] = (float)m2;
            g_stats[3] = (float)(1.0 / sqrt(v2 + (double)LN_EPS));
            g_ctr = 0;
            g_predctr = 0;
        }
    }
}

// ---------------------------------------------------------------------------
// Kernel C (D==32, F==128): warp-per-node LDG.128 pair gather. Quad fp16
// tree-sum (3 HADD2/component per 4 rows) + packed f32x2 accumulation
// (add.rn.f32x2) — cuts the accumulate instruction stream ~40%.
// Direct permuted epilogue store (lane owns float4 column 2*lo+hi).
// ---------------------------------------------------------------------------
__global__ void __launch_bounds__(256)
k_main16(const float* __restrict__ h, const float* __restrict__ old_z,
         const float* __restrict__ tau1, const float* __restrict__ tau2,
         const int* __restrict__ nbr,
         float* __restrict__ out_h, float* __restrict__ out_z, int n) {
    int w = (int)((blockIdx.x * blockDim.x + threadIdx.x) >> 5);
    int lane = threadIdx.x & 31;
    if (w >= n) return;
    int hi = lane >> 4;
    int lo = lane & 15;

    int j = __ldg(&nbr[(size_t)w * 32 + lane]);

    const uint4* hp = (const uint4*)g_h16;   // 16B granules; row stride = 16
    uint4 buf[2][4];
    #pragma unroll
    for (int d = 0; d < 4; d++) {
        int idx = __shfl_sync(0xffffffffu, j, 2 * d + hi);
        buf[0][d] = __ldg(&hp[(size_t)idx * 16 + lo]);
    }

    // packed f32x2 accumulators: a01 = cols {0,1}, a23 = {2,3}, ...
    unsigned long long a01 = 0ull, a23 = 0ull, a45 = 0ull, a67 = 0ull;
    #pragma unroll
    for (int g = 0; g < 4; g++) {
        const int cur = g & 1;
        if (g < 3) {
            #pragma unroll
            for (int d = 0; d < 4; d++) {
                int dd = (g + 1) * 4 + d;
                int idx = __shfl_sync(0xffffffffu, j, 2 * dd + hi);
                buf[cur ^ 1][d] = __ldg(&hp[(size_t)idx * 16 + lo]);
            }
        }
        // quad fp16 tree-sum over the 4 rows of this group, per component
        uint4 b0 = buf[cur][0], b1 = buf[cur][1], b2 = buf[cur][2], b3 = buf[cur][3];
        __half2 qx = __hadd2(__hadd2(*(__half2*)&b0.x, *(__half2*)&b1.x),
                             __hadd2(*(__half2*)&b2.x, *(__half2*)&b3.x));
        __half2 qy = __hadd2(__hadd2(*(__half2*)&b0.y, *(__half2*)&b1.y),
                             __hadd2(*(__half2*)&b2.y, *(__half2*)&b3.y));
        __half2 qz = __hadd2(__hadd2(*(__half2*)&b0.z, *(__half2*)&b1.z),
                             __hadd2(*(__half2*)&b2.z, *(__half2*)&b3.z));
        __half2 qw = __hadd2(__hadd2(*(__half2*)&b0.w, *(__half2*)&b1.w),
                             __hadd2(*(__half2*)&b2.w, *(__half2*)&b3.w));
        float2 fx = __half22float2(qx);
        float2 fy = __half22float2(qy);
        float2 fz = __half22float2(qz);
        float2 fw = __half22float2(qw);
        addf32x2(a01, *(unsigned long long*)&fx);
        addf32x2(a23, *(unsigned long long*)&fy);
        addf32x2(a45, *(unsigned long long*)&fz);
        addf32x2(a67, *(unsigned long long*)&fw);
    }
    // combine even-row half with odd-row half (packed shfl + f32x2 add)
    {
        unsigned long long o01 = __shfl_xor_sync(0xffffffffu, a01, 16);
        unsigned long long o23 = __shfl_xor_sync(0xffffffffu, a23, 16);
        unsigned long long o45 = __shfl_xor_sync(0xffffffffu, a45, 16);
        unsigned long long o67 = __shfl_xor_sync(0xffffffffu, a67, 16);
        addf32x2(a01, o01);
        addf32x2(a23, o23);
        addf32x2(a45, o45);
        addf32x2(a67, o67);
    }

    float nf1 = (g_f1[w] - g_stats[0]) * g_stats[1];
    float nf2 = (g_f2[w] - g_stats[2]) * g_stats[3];
    float t1 = __ldg(tau1), t2 = __ldg(tau2);
    float z = __frcp_rn(1.f + __expf(nf1 - t1)) * __frcp_rn(1.f + __expf(nf2 - t2));
    float gate = fminf(__ldg(&old_z[w]), z);

    // direct permuted store: this lane owns float4 column-index c4 = 2*lo+hi
    int c4 = 2 * lo + hi;
    float2 p0 = *(float2*)&a01;
    float2 p1 = *(float2*)&a23;
    float2 p2 = *(float2*)&a45;
    float2 p3 = *(float2*)&a67;
    float a0 = hi ? p2.x : p0.x;
    float a1 = hi ? p2.y : p0.y;
    float a2 = hi ? p3.x : p1.x;
    float a3 = hi ? p3.y : p1.y;

    float4 hc = __ldg(&((const float4*)h)[(size_t)w * 32 + c4]);
    float4 o;
    o.x = hc.x + gate * fmaxf(a0, 0.f);
    o.y = hc.y + gate * fmaxf(a1, 0.f);
    o.z = hc.z + gate * fmaxf(a2, 0.f);
    o.w = hc.w + gate * fmaxf(a3, 0.f);
    ((float4*)out_h)[(size_t)w * 32 + c4] = o;
    if (lane == 0) out_z[w] = z;
}

// ---------------------------------------------------------------------------
// Generic fallback path (any D / F multiple of 4): exact f32 gather.
// ---------------------------------------------------------------------------
__global__ void k_pred_gen(const float* __restrict__ logits, int n, int C) {
    int i = blockIdx.x * blockDim.x + threadIdx.x;
    if (i >= n) return;
    const float* row = logits + (size_t)i * C;
    float best = __ldg(&row[0]);
    int bi = 0;
    for (int c = 1; c < C; c++) {
        float v = __ldg(&row[c]);
        if (v > best) { best = v; bi = c; }
    }
    g_pred[i] = (unsigned char)bi;
}

__global__ void k_feat_gen(const int* __restrict__ nbr, int n, int D, int C) {
    int i = blockIdx.x * blockDim.x + threadIdx.x;
    float f1 = 0.f, f2 = 0.f;
    if (i < n) {
        unsigned int cnt[4] = {0u, 0u, 0u, 0u};
        const int* row = nbr + (size_t)i * D;
        for (int d = 0; d < D; d++) {
            int j = __ldg(&row[d]);
            int p = (int)g_pred[j];
            cnt[p >> 2] += 1u << ((p & 3) * 8);
        }
        int cp = (int)g_pred[i];
        f1 = (float)((cnt[cp >> 2] >> ((cp & 3) * 8)) & 0xffu);
        float s = 0.f;
        for (int w = 0; w < 4; w++) {
            unsigned int v = cnt[w];
            for (int b = 0; b < 4; b++) {
                float k = (float)((v >> (b * 8)) & 0xffu);
                float p = fmaxf(k, CLAMP_MIN);
                s += p * logf(p);
            }
        }
        f2 = -s;
        g_f1[i] = f1;
        g_f2[i] = f2;
    }
    double s1 = (double)f1, q1 = (double)f1 * f1;
    double s2 = (double)f2, q2 = (double)f2 * f2;
    __shared__ double sh[4][8];
    int lane = threadIdx.x & 31, wid = threadIdx.x >> 5;
    for (int o = 16; o; o >>= 1) {
        s1 += __shfl_down_sync(0xffffffffu, s1, o);
        q1 += __shfl_down_sync(0xffffffffu, q1, o);
        s2 += __shfl_down_sync(0xffffffffu, s2, o);
        q2 += __shfl_down_sync(0xffffffffu, q2, o);
    }
    if (lane == 0) { sh[0][wid] = s1; sh[1][wid] = q1; sh[2][wid] = s2; sh[3][wid] = q2; }
    __syncthreads();
    if (threadIdx.x == 0) {
        s1 = 0; q1 = 0; s2 = 0; q2 = 0;
        for (int k = 0; k < 8; k++) { s1 += sh[0][k]; q1 += sh[1][k]; s2 += sh[2][k]; q2 += sh[3][k]; }
        g_part[0 * MAXB + blockIdx.x] = s1;
        g_part[1 * MAXB + blockIdx.x] = q1;
        g_part[2 * MAXB + blockIdx.x] = s2;
        g_part[3 * MAXB + blockIdx.x] = q2;
    }
}

__global__ void k_stats(int n, int nb) {
    double s1 = 0, q1 = 0, s2 = 0, q2 = 0;
    for (int b = threadIdx.x; b < nb; b += blockDim.x) {
        s1 += g_part[0 * MAXB + b];
        q1 += g_part[1 * MAXB + b];
        s2 += g_part[2 * MAXB + b];
        q2 += g_part[3 * MAXB + b];
    }
    __shared__ double sh[4][32];
    int lane = threadIdx.x & 31, wid = threadIdx.x >> 5;
    for (int o = 16; o; o >>= 1) {
        s1 += __shfl_down_sync(0xffffffffu, s1, o);
        q1 += __shfl_down_sync(0xffffffffu, q1, o);
        s2 += __shfl_down_sync(0xffffffffu, s2, o);
        q2 += __shfl_down_sync(0xffffffffu, q2, o);
    }
    if (lane == 0) { sh[0][wid] = s1; sh[1][wid] = q1; sh[2][wid] = s2; sh[3][wid] = q2; }
    __syncthreads();
    if (threadIdx.x == 0) {
        int nw = blockDim.x >> 5;
        s1 = 0; q1 = 0; s2 = 0; q2 = 0;
        for (int k = 0; k < nw; k++) { s1 += sh[0][k]; q1 += sh[1][k]; s2 += sh[2][k]; q2 += sh[3][k]; }
        double inv_n = 1.0 / (double)n;
        double m1 = s1 * inv_n, m2 = s2 * inv_n;
        double v1 = q1 * inv_n - m1 * m1;
        double v2 = q2 * inv_n - m2 * m2;
        g_stats[0] = (float)m1;
        g_stats[1] = (float)(1.0 / sqrt(v1 + (double)LN_EPS));
        g_stats[2] = (float)m2;
        g_stats[3] = (float)(1.0 / sqrt(v2 + (double)LN_EPS));
    }
}

__global__ void __launch_bounds__(256)
k_main_gen(const float* __restrict__ h, const float* __restrict__ old_z,
           const float* __restrict__ tau1, const float* __restrict__ tau2,
           const int* __restrict__ nbr,
           float* __restrict__ out_h, float* __restrict__ out_z,
           int n, int F4, int D) {
    int w = (int)((blockIdx.x * blockDim.x + threadIdx.x) >> 5);
    int lane = threadIdx.x & 31;
    if (w >= n) return;

    float nf1 = (g_f1[w] - g_stats[0]) * g_stats[1];
    float nf2 = (g_f2[w] - g_stats[2]) * g_stats[3];
    float t1 = __ldg(tau1), t2 = __ldg(tau2);
    float z = __frcp_rn(1.f + __expf(nf1 - t1)) * __frcp_rn(1.f + __expf(nf2 - t2));
    float gate = fminf(__ldg(&old_z[w]), z);

    const float4* hp = (const float4*)h;
    for (int col = lane; col < F4; col += 32) {
        float a0 = 0.f, a1 = 0.f, a2 = 0.f, a3 = 0.f;
        for (int d = 0; d < D; d++) {
            int idx = __ldg(&nbr[(size_t)w * D + d]);
            float4 v = __ldg(&hp[(size_t)idx * F4 + col]);
            a0 += v.x; a1 += v.y; a2 += v.z; a3 += v.w;
        }
        float4 hc = __ldg(&hp[(size_t)w * F4 + col]);
        float4 o;
        o.x = hc.x + gate * fmaxf(a0, 0.f);
        o.y = hc.y + gate * fmaxf(a1, 0.f);
        o.z = hc.z + gate * fmaxf(a2, 0.f);
        o.w = hc.w + gate * fmaxf(a3, 0.f);
        ((float4*)out_h)[(size_t)w * F4 + col] = o;
    }
    if (lane == 0) out_z[w] = z;
}

extern "C" void kernel_launch(void* const* d_in, const int* in_sizes, int n_in,
                              void* d_out, int out_size) {
    const float* h      = (const float*)d_in[0];
    const float* logits = (const float*)d_in[1];
    const float* old_z  = (const float*)d_in[2];
    const float* tau1   = (const float*)d_in[3];
    const float* tau2   = (const float*)d_in[4];
    const int*   nbr    = (const int*)d_in[5];

    int n = in_sizes[2];                 // old_z length = N
    int F = in_sizes[0] / n;             // 128
    int C = in_sizes[1] / n;             // 16
    int D = in_sizes[5] / n;             // 32

    float* out_h = (float*)d_out;
    float* out_z = out_h + (size_t)n * F;

    if (D == 32 && F == 128 && C == 16 && n <= MAXN) {
        int nbfeat = (n + 255) / 256;    // 196 feat blocks
        int grid = nbfeat + 1480;        // + 1480 conversion blocks
        k_featconv<<<grid, 256>>>(nbr, logits, h, n, nbfeat, n * 32);
        int blocks = (n + 7) / 8;        // warp-per-node, 8 warps/block
        k_main16<<<blocks, 256>>>(h, old_z, tau1, tau2, nbr, out_h, out_z, n);
    } else {
        int tb = 256;
        int nb = (n + tb - 1) / tb;
        int F4 = F / 4;
        k_pred_gen<<<nb, tb>>>(logits, n, C);
        k_feat_gen<<<nb, tb>>>(nbr, n, D, C);
        k_stats<<<1, 256>>>(n, nb);
        int blocks = (n + 7) / 8;
        k_main_gen<<<blocks, tb>>>(h, old_z, tau1, tau2, nbr, out_h, out_z, n, F4, D);
    }
}